// round 1
// baseline (speedup 1.0000x reference)
#include <cuda_runtime.h>
#include <math.h>

#define Bn   8
#define NTn  8192
#define NSn  2048
#define CT   128
#define CS   256
#define CIN  384
#define CH   256
#define CO   128
#define Mtot (Bn * NTn)

// Scratch (static device globals — no runtime allocation)
__device__ float g_combined[(size_t)Mtot * CIN];  // 96 MB
__device__ float g_hidden[(size_t)Mtot * CH];     // 64 MB

// ---------------------------------------------------------------------------
// Kernel 1: KNN (K=3) inverse-distance interpolate + build combined matrix
// grid = (NT/256, B), block = 256
// ---------------------------------------------------------------------------
__global__ __launch_bounds__(256) void knn_combined_kernel(
    const float* __restrict__ x_t, const float* __restrict__ pos_t,
    const float* __restrict__ x_s, const float* __restrict__ pos_s)
{
    __shared__ float4 sp[NSn];        // 32 KB: source positions for this batch
    __shared__ int    sidx[256][3];
    __shared__ float  sw[256][3];

    const int b   = blockIdx.y;
    const int tid = threadIdx.x;

    // Load this batch's source positions into SMEM as float4
    const float* ps = pos_s + (size_t)b * NSn * 3;
    for (int j = tid; j < NSn; j += 256) {
        sp[j] = make_float4(ps[3 * j], ps[3 * j + 1], ps[3 * j + 2], 0.f);
    }
    __syncthreads();

    const int t0 = b * NTn + blockIdx.x * 256;
    const int t  = t0 + tid;
    const float tx = pos_t[3 * t], ty = pos_t[3 * t + 1], tz = pos_t[3 * t + 2];

    float d0 = 3.4e38f, d1 = 3.4e38f, d2 = 3.4e38f;
    int   i0 = 0, i1 = 0, i2 = 0;

#pragma unroll 4
    for (int j = 0; j < NSn; j++) {
        float4 s = sp[j];                     // LDS.128 broadcast
        float dx = tx - s.x, dy = ty - s.y, dz = tz - s.z;
        float d  = fmaf(dx, dx, fmaf(dy, dy, dz * dz));
        if (d < d2) {                         // rarely taken
            if (d < d1) {
                d2 = d1; i2 = i1;
                if (d < d0) { d1 = d0; i1 = i0; d0 = d; i0 = j; }
                else        { d1 = d;  i1 = j; }
            } else { d2 = d; i2 = j; }
        }
    }

    float w0 = 1.f / fmaxf(d0, 1e-16f);
    float w1 = 1.f / fmaxf(d1, 1e-16f);
    float w2 = 1.f / fmaxf(d2, 1e-16f);
    float inv = 1.f / (w0 + w1 + w2);
    sidx[tid][0] = i0; sidx[tid][1] = i1; sidx[tid][2] = i2;
    sw[tid][0] = w0 * inv; sw[tid][1] = w1 * inv; sw[tid][2] = w2 * inv;
    __syncthreads();

    // Phase 2: cooperative, coalesced feature gather. thread = channel (CS=256)
    const float* xsb = x_s + (size_t)b * NSn * CS;
    const int c = tid;
    for (int tt = 0; tt < 256; tt++) {
        const int tg = t0 + tt;
        float v = sw[tt][0] * xsb[(size_t)sidx[tt][0] * CS + c]
                + sw[tt][1] * xsb[(size_t)sidx[tt][1] * CS + c]
                + sw[tt][2] * xsb[(size_t)sidx[tt][2] * CS + c];
        g_combined[(size_t)tg * CIN + CT + c] = v;
        if (c < CT)
            g_combined[(size_t)tg * CIN + c] = x_t[(size_t)tg * CT + c];
    }
}

// ---------------------------------------------------------------------------
// SGEMM: 128x128 tile, 256 threads, 8x8 per thread, K-tile 8.
// Dual-phase: C = relu( A0@B0 [+ A1@B1] + bias0 [+ bias1] )
// ---------------------------------------------------------------------------
__device__ __forceinline__ void gemm_phase(
    const float* __restrict__ A, const float* __restrict__ Bm,
    int K, int lda, int N, int bm, int bn,
    float (&acc)[8][8], float (*As)[128], float (*Bs)[128],
    int tid, int row0, int col0)
{
    for (int k0 = 0; k0 < K; k0 += 8) {
        // global loads first (latency overlaps barrier wait)
        const int r  = tid >> 1, kq = (tid & 1) * 4;
        float4 a = *(const float4*)&A[(size_t)(bm + r) * lda + k0 + kq];
        const int kb = tid >> 5, cb = (tid & 31) * 4;
        float4 bv = *(const float4*)&Bm[(size_t)(k0 + kb) * N + bn + cb];

        __syncthreads();   // previous iteration's readers done
        As[kq + 0][r] = a.x; As[kq + 1][r] = a.y;
        As[kq + 2][r] = a.z; As[kq + 3][r] = a.w;
        *(float4*)&Bs[kb][cb] = bv;
        __syncthreads();

#pragma unroll
        for (int k = 0; k < 8; k++) {
            float ar[8], br[8];
            *(float4*)&ar[0] = *(const float4*)&As[k][row0];
            *(float4*)&ar[4] = *(const float4*)&As[k][row0 + 4];
            *(float4*)&br[0] = *(const float4*)&Bs[k][col0];
            *(float4*)&br[4] = *(const float4*)&Bs[k][col0 + 4];
#pragma unroll
            for (int i = 0; i < 8; i++)
#pragma unroll
                for (int j = 0; j < 8; j++)
                    acc[i][j] = fmaf(ar[i], br[j], acc[i][j]);
        }
    }
}

__global__ __launch_bounds__(256, 2) void sgemm_dual_relu(
    const float* __restrict__ A0, const float* __restrict__ B0, int K0, int lda0,
    const float* __restrict__ A1, const float* __restrict__ B1, int K1, int lda1,
    const float* __restrict__ bias0, const float* __restrict__ bias1,
    float* __restrict__ C, int N)
{
    __shared__ float As[8][128];
    __shared__ float Bs[8][128];

    float acc[8][8];
#pragma unroll
    for (int i = 0; i < 8; i++)
#pragma unroll
        for (int j = 0; j < 8; j++) acc[i][j] = 0.f;

    const int tid = threadIdx.x;
    const int bm = blockIdx.x * 128, bn = blockIdx.y * 128;
    const int row0 = (tid / 16) * 8, col0 = (tid % 16) * 8;

    gemm_phase(A0, B0, K0, lda0, N, bm, bn, acc, As, Bs, tid, row0, col0);
    if (K1 > 0)
        gemm_phase(A1, B1, K1, lda1, N, bm, bn, acc, As, Bs, tid, row0, col0);

    float bb[8];
#pragma unroll
    for (int j = 0; j < 8; j++) {
        bb[j] = bias0[bn + col0 + j];
        if (bias1) bb[j] += bias1[bn + col0 + j];
    }

#pragma unroll
    for (int i = 0; i < 8; i++) {
        const size_t row = (size_t)(bm + row0 + i);
#pragma unroll
        for (int j = 0; j < 8; j += 4) {
            float4 v;
            v.x = fmaxf(acc[i][j + 0] + bb[j + 0], 0.f);
            v.y = fmaxf(acc[i][j + 1] + bb[j + 1], 0.f);
            v.z = fmaxf(acc[i][j + 2] + bb[j + 2], 0.f);
            v.w = fmaxf(acc[i][j + 3] + bb[j + 3], 0.f);
            *(float4*)&C[row * N + bn + col0 + j] = v;
        }
    }
}

// ---------------------------------------------------------------------------
extern "C" void kernel_launch(void* const* d_in, const int* in_sizes, int n_in,
                              void* d_out, int out_size)
{
    const float* x_t   = (const float*)d_in[0];
    const float* pos_t = (const float*)d_in[1];
    const float* x_s   = (const float*)d_in[3];
    const float* pos_s = (const float*)d_in[4];
    const float* W1    = (const float*)d_in[6];
    const float* b1    = (const float*)d_in[7];
    const float* W2    = (const float*)d_in[8];
    const float* b2    = (const float*)d_in[9];
    const float* Ws    = (const float*)d_in[10];
    const float* bs    = (const float*)d_in[11];
    float* out = (float*)d_out;

    float *comb, *hid;
    cudaGetSymbolAddress((void**)&comb, g_combined);
    cudaGetSymbolAddress((void**)&hid, g_hidden);

    // 1) KNN interpolate + build combined [65536, 384]
    knn_combined_kernel<<<dim3(NTn / 256, Bn), 256>>>(x_t, pos_t, x_s, pos_s);

    // 2) hidden = relu(combined @ W1 + b1)   [65536, 256]
    sgemm_dual_relu<<<dim3(Mtot / 128, CH / 128), 256>>>(
        comb, W1, CIN, CIN, nullptr, nullptr, 0, 0, b1, nullptr, hid, CH);

    // 3) out = relu(hidden @ W2 + combined @ Ws + b2 + bs)   [65536, 128]
    sgemm_dual_relu<<<dim3(Mtot / 128, CO / 128), 256>>>(
        hid, W2, CH, CH, comb, Ws, CIN, CIN, b2, bs, out, CO);
}

// round 4
// speedup vs baseline: 2.1194x; 2.1194x over previous
#include <cuda_runtime.h>
#include <cuda_bf16.h>
#include <math.h>
#include <stdint.h>

#define Bn   8
#define NTn  8192
#define NSn  2048
#define CT   128
#define CS   256
#define CIN  384
#define CH   256
#define CO   128
#define Mtot (Bn * NTn)

// ---------------------------------------------------------------------------
// Device scratch (static — no runtime allocation)
// ---------------------------------------------------------------------------
__device__ __nv_bfloat16 g_comb_hi[(size_t)Mtot * CIN];
__device__ __nv_bfloat16 g_comb_lo[(size_t)Mtot * CIN];
__device__ __nv_bfloat16 g_hid_hi[(size_t)Mtot * CH];
__device__ __nv_bfloat16 g_hid_lo[(size_t)Mtot * CH];
__device__ __nv_bfloat16 g_w1t_hi[CH * CIN];
__device__ __nv_bfloat16 g_w1t_lo[CH * CIN];
__device__ __nv_bfloat16 g_w2t_hi[CO * CH];
__device__ __nv_bfloat16 g_w2t_lo[CO * CH];
__device__ __nv_bfloat16 g_wst_hi[CO * CIN];
__device__ __nv_bfloat16 g_wst_lo[CO * CIN];

// ---------------------------------------------------------------------------
// Helpers
// ---------------------------------------------------------------------------
__device__ __forceinline__ uint32_t smem_u32(const void* p) {
    uint32_t a;
    asm("{ .reg .u64 t; cvta.to.shared.u64 t, %1; cvt.u32.u64 %0, t; }" : "=r"(a) : "l"(p));
    return a;
}
#define CP16(smem_addr, gptr) \
    asm volatile("cp.async.cg.shared.global [%0], [%1], 16;" :: "r"(smem_addr), "l"(gptr))
#define CP_COMMIT() asm volatile("cp.async.commit_group;" ::: "memory")
#define CP_WAIT1()  asm volatile("cp.async.wait_group 1;" ::: "memory")
#define CP_WAIT0()  asm volatile("cp.async.wait_group 0;" ::: "memory")

__device__ __forceinline__ void ldsm4(uint32_t& r0, uint32_t& r1, uint32_t& r2, uint32_t& r3,
                                      uint32_t a) {
    asm volatile("ldmatrix.sync.aligned.m8n8.x4.shared.b16 {%0,%1,%2,%3}, [%4];"
                 : "=r"(r0), "=r"(r1), "=r"(r2), "=r"(r3) : "r"(a));
}
__device__ __forceinline__ void mma16816(float* d, uint32_t a0, uint32_t a1, uint32_t a2,
                                         uint32_t a3, uint32_t b0, uint32_t b1) {
    asm volatile("mma.sync.aligned.m16n8k16.row.col.f32.bf16.bf16.f32 "
                 "{%0,%1,%2,%3}, {%4,%5,%6,%7}, {%8,%9}, {%0,%1,%2,%3};"
                 : "+f"(d[0]), "+f"(d[1]), "+f"(d[2]), "+f"(d[3])
                 : "r"(a0), "r"(a1), "r"(a2), "r"(a3), "r"(b0), "r"(b1));
}
__device__ __forceinline__ void split2(float v, __nv_bfloat16& h, __nv_bfloat16& l) {
    h = __float2bfloat16(v);
    l = __float2bfloat16(v - __bfloat162float(h));
}
__device__ __forceinline__ uint32_t pack2(__nv_bfloat16 a, __nv_bfloat16 b) {
    __nv_bfloat162 t; t.x = a; t.y = b;
    return *reinterpret_cast<uint32_t*>(&t);
}

// ---------------------------------------------------------------------------
// SMEM stage layout: 4 tensors [128 rows x 32 bf16], padded pitch 80 B
// (bank windows 20r mod 32 -> conflict-free ldmatrix)
// ---------------------------------------------------------------------------
#define PITCH  80
#define T_AH   0
#define T_AL   10240
#define T_BH   20480
#define T_BL   30720
#define STAGE  40960
#define GSMEM  (2 * STAGE)

__device__ __forceinline__ void load_stage(uint32_t st,
    const __nv_bfloat16* Ah, const __nv_bfloat16* Al,
    const __nv_bfloat16* Bh, const __nv_bfloat16* Bl,
    int ld, int k0, int tid)
{
    const __nv_bfloat16* gp[4] = {Ah, Al, Bh, Bl};
#pragma unroll
    for (int i = 0; i < 8; i++) {
        const int t  = i >> 1;                      // compile-time tensor id
        const int rr = (i & 1) * 64 + (tid >> 2);
        const int q  = tid & 3;
        CP16(st + t * 10240 + rr * PITCH + q * 16, gp[t] + (size_t)rr * ld + k0 + q * 8);
    }
    CP_COMMIT();
}

__device__ __forceinline__ void mma_stage(uint32_t st, int warp_m, int warp_n, int lane,
                                          float acc[2][8][4])
{
    const uint32_t arow0 = warp_m * 32 + (lane & 15);
    const uint32_t ahalf = (lane >> 4) * 16;
    const uint32_t brow  = warp_n * 64 + (lane & 7) + ((lane >> 4) << 3);
    const uint32_t bhalf = ((lane >> 3) & 1) * 16;
#pragma unroll
    for (int ks = 0; ks < 2; ks++) {
        const uint32_t ko = ks * 32;
#pragma unroll
        for (int p = 0; p < 3; p++) {          // Ah*Bh, Ah*Bl, Al*Bh
            const uint32_t aoff = (p == 2) ? T_AL : T_AH;
            const uint32_t boff = (p == 1) ? T_BL : T_BH;
            uint32_t a[2][4];
#pragma unroll
            for (int mt = 0; mt < 2; mt++)
                ldsm4(a[mt][0], a[mt][1], a[mt][2], a[mt][3],
                      st + aoff + (arow0 + mt * 16) * PITCH + ko + ahalf);
            uint32_t b[16];
#pragma unroll
            for (int j = 0; j < 4; j++)
                ldsm4(b[4*j], b[4*j+1], b[4*j+2], b[4*j+3],
                      st + boff + (brow + j * 16) * PITCH + ko + bhalf);
#pragma unroll
            for (int mt = 0; mt < 2; mt++)
#pragma unroll
                for (int nt = 0; nt < 8; nt++)
                    mma16816(acc[mt][nt], a[mt][0], a[mt][1], a[mt][2], a[mt][3],
                             b[2*nt], b[2*nt+1]);
        }
    }
}

__device__ __forceinline__ void gemm_phase(uint32_t sb,
    const __nv_bfloat16* Ah, const __nv_bfloat16* Al,
    const __nv_bfloat16* Bh, const __nv_bfloat16* Bl,
    int ld, int kchunks, int tid, int warp_m, int warp_n, int lane,
    float acc[2][8][4])
{
    load_stage(sb, Ah, Al, Bh, Bl, ld, 0, tid);
    for (int c = 0; c < kchunks; c++) {
        if (c + 1 < kchunks) {
            load_stage(sb + ((c + 1) & 1) * STAGE, Ah, Al, Bh, Bl, ld, (c + 1) * 32, tid);
            CP_WAIT1();
        } else {
            CP_WAIT0();
        }
        __syncthreads();
        mma_stage(sb + (c & 1) * STAGE, warp_m, warp_n, lane, acc);
        __syncthreads();
    }
}

// ---------------------------------------------------------------------------
// Weight prep: transpose + bf16 split
// ---------------------------------------------------------------------------
__global__ void prep_weights(const float* __restrict__ W1, const float* __restrict__ W2,
                             const float* __restrict__ Ws) {
    int i = blockIdx.x * blockDim.x + threadIdx.x;
    if (i < CH * CIN) {
        int n = i / CIN, k = i % CIN;
        split2(W1[(size_t)k * CH + n], g_w1t_hi[i], g_w1t_lo[i]);
    }
    if (i < CO * CH) {
        int n = i / CH, k = i % CH;
        split2(W2[(size_t)k * CO + n], g_w2t_hi[i], g_w2t_lo[i]);
    }
    if (i < CO * CIN) {
        int n = i / CIN, k = i % CIN;
        split2(Ws[(size_t)k * CO + n], g_wst_hi[i], g_wst_lo[i]);
    }
}

// ---------------------------------------------------------------------------
// KNN: 64 targets/CTA, 4-way source split (512 sources/thread), merge 12->3
// ---------------------------------------------------------------------------
__global__ __launch_bounds__(256) void knn_kernel(
    const float* __restrict__ x_t, const float* __restrict__ pos_t,
    const float* __restrict__ x_s, const float* __restrict__ pos_s)
{
    __shared__ float4 sp[NSn];        // 32 KB
    __shared__ float  cd[64][12];
    __shared__ int    ci[64][12];
    __shared__ float  swt[64][3];
    __shared__ int    sit[64][3];

    const int b   = blockIdx.y;
    const int tid = threadIdx.x;

    const float* ps = pos_s + (size_t)b * NSn * 3;
    for (int j = tid; j < NSn; j += 256)
        sp[j] = make_float4(ps[3*j], ps[3*j+1], ps[3*j+2], 0.f);
    __syncthreads();

    const int tt = tid & 63, sq = tid >> 6;
    const int t0 = b * NTn + blockIdx.x * 64;
    const int t  = t0 + tt;
    const float tx = pos_t[3*t], ty = pos_t[3*t+1], tz = pos_t[3*t+2];

    float d0 = 3.4e38f, d1 = 3.4e38f, d2 = 3.4e38f;
    int   i0 = 0, i1 = 0, i2 = 0;
    const int jb = sq * 512;
#pragma unroll 4
    for (int j = jb; j < jb + 512; j++) {
        float4 s = sp[j];
        float dx = tx - s.x, dy = ty - s.y, dz = tz - s.z;
        float d  = fmaf(dx, dx, fmaf(dy, dy, dz * dz));
        if (d < d2) {
            if (d < d1) {
                d2 = d1; i2 = i1;
                if (d < d0) { d1 = d0; i1 = i0; d0 = d; i0 = j; }
                else        { d1 = d;  i1 = j; }
            } else { d2 = d; i2 = j; }
        }
    }
    cd[tt][sq*3+0] = d0; ci[tt][sq*3+0] = i0;
    cd[tt][sq*3+1] = d1; ci[tt][sq*3+1] = i1;
    cd[tt][sq*3+2] = d2; ci[tt][sq*3+2] = i2;
    __syncthreads();

    if (tid < 64) {
        float e0 = 3.4e38f, e1 = 3.4e38f, e2 = 3.4e38f;
        int   j0 = 0, j1 = 0, j2 = 0;
#pragma unroll
        for (int k = 0; k < 12; k++) {
            float d = cd[tid][k]; int ii = ci[tid][k];
            if (d < e2) {
                if (d < e1) {
                    e2 = e1; j2 = j1;
                    if (d < e0) { e1 = e0; j1 = j0; e0 = d; j0 = ii; }
                    else        { e1 = d;  j1 = ii; }
                } else { e2 = d; j2 = ii; }
            }
        }
        float w0 = 1.f / fmaxf(e0, 1e-16f);
        float w1 = 1.f / fmaxf(e1, 1e-16f);
        float w2 = 1.f / fmaxf(e2, 1e-16f);
        float inv = 1.f / (w0 + w1 + w2);
        swt[tid][0] = w0 * inv; swt[tid][1] = w1 * inv; swt[tid][2] = w2 * inv;
        sit[tid][0] = j0; sit[tid][1] = j1; sit[tid][2] = j2;
    }
    __syncthreads();

    // Gather: thread = channel (256), coalesced feature reads/writes
    const float* xsb = x_s + (size_t)b * NSn * CS;
    const int c = tid;
    for (int u = 0; u < 64; u++) {
        const int tg = t0 + u;
        float v = swt[u][0] * xsb[(size_t)sit[u][0] * CS + c]
                + swt[u][1] * xsb[(size_t)sit[u][1] * CS + c]
                + swt[u][2] * xsb[(size_t)sit[u][2] * CS + c];
        __nv_bfloat16 h, l;
        split2(v, h, l);
        g_comb_hi[(size_t)tg * CIN + CT + c] = h;
        g_comb_lo[(size_t)tg * CIN + CT + c] = l;
        if (c < CT) {
            split2(x_t[(size_t)tg * CT + c], h, l);
            g_comb_hi[(size_t)tg * CIN + c] = h;
            g_comb_lo[(size_t)tg * CIN + c] = l;
        }
    }
}

// ---------------------------------------------------------------------------
// GEMM1: hid = relu(comb @ W1 + b1), M=65536 N=256 K=384 (bf16 split x3)
// grid (2, 512): N fastest so N-pairs share the A tile in L2
// ---------------------------------------------------------------------------
__global__ __launch_bounds__(256) void gemm1_kernel(const float* __restrict__ b1) {
    extern __shared__ char smem[];
    const uint32_t sb = smem_u32(smem);
    const int tid = threadIdx.x, lane = tid & 31, wid = tid >> 5;
    const int warp_m = wid >> 1, warp_n = wid & 1;
    const int bn = blockIdx.x * 128, bm = blockIdx.y * 128;

    float acc[2][8][4] = {};
    gemm_phase(sb, g_comb_hi + (size_t)bm * CIN, g_comb_lo + (size_t)bm * CIN,
               g_w1t_hi + (size_t)bn * CIN, g_w1t_lo + (size_t)bn * CIN,
               CIN, 12, tid, warp_m, warp_n, lane, acc);

    uint32_t* dh = (uint32_t*)g_hid_hi;
    uint32_t* dl = (uint32_t*)g_hid_lo;
#pragma unroll
    for (int mt = 0; mt < 2; mt++) {
#pragma unroll
        for (int nt = 0; nt < 8; nt++) {
            const int col = bn + warp_n * 64 + nt * 8 + (lane & 3) * 2;
            const float bb0 = __ldg(b1 + col), bb1 = __ldg(b1 + col + 1);
            const int row = bm + warp_m * 32 + mt * 16 + (lane >> 2);
#pragma unroll
            for (int h = 0; h < 2; h++) {
                const int r = row + h * 8;
                float v0 = fmaxf(acc[mt][nt][2*h+0] + bb0, 0.f);
                float v1 = fmaxf(acc[mt][nt][2*h+1] + bb1, 0.f);
                __nv_bfloat16 h0, l0, h1, l1;
                split2(v0, h0, l0);
                split2(v1, h1, l1);
                const size_t w = ((size_t)r * CH + col) >> 1;
                dh[w] = pack2(h0, h1);
                dl[w] = pack2(l0, l1);
            }
        }
    }
}

// ---------------------------------------------------------------------------
// GEMM2: out = relu(hid @ W2 + comb @ Ws + b2 + bs), M=65536 N=128
// ---------------------------------------------------------------------------
__global__ __launch_bounds__(256) void gemm2_kernel(
    const float* __restrict__ b2, const float* __restrict__ bs, float* __restrict__ out)
{
    extern __shared__ char smem[];
    const uint32_t sb = smem_u32(smem);
    const int tid = threadIdx.x, lane = tid & 31, wid = tid >> 5;
    const int warp_m = wid >> 1, warp_n = wid & 1;
    const int bm = blockIdx.x * 128;

    float acc[2][8][4] = {};
    gemm_phase(sb, g_hid_hi + (size_t)bm * CH, g_hid_lo + (size_t)bm * CH,
               g_w2t_hi, g_w2t_lo, CH, 8, tid, warp_m, warp_n, lane, acc);
    gemm_phase(sb, g_comb_hi + (size_t)bm * CIN, g_comb_lo + (size_t)bm * CIN,
               g_wst_hi, g_wst_lo, CIN, 12, tid, warp_m, warp_n, lane, acc);

#pragma unroll
    for (int mt = 0; mt < 2; mt++) {
#pragma unroll
        for (int nt = 0; nt < 8; nt++) {
            const int col = warp_n * 64 + nt * 8 + (lane & 3) * 2;
            const float bb0 = __ldg(b2 + col) + __ldg(bs + col);
            const float bb1 = __ldg(b2 + col + 1) + __ldg(bs + col + 1);
            const int row = bm + warp_m * 32 + mt * 16 + (lane >> 2);
#pragma unroll
            for (int h = 0; h < 2; h++) {
                const int r = row + h * 8;
                float2 v;
                v.x = fmaxf(acc[mt][nt][2*h+0] + bb0, 0.f);
                v.y = fmaxf(acc[mt][nt][2*h+1] + bb1, 0.f);
                *(float2*)&out[(size_t)r * CO + col] = v;
            }
        }
    }
}

// ---------------------------------------------------------------------------
extern "C" void kernel_launch(void* const* d_in, const int* in_sizes, int n_in,
                              void* d_out, int out_size)
{
    const float* x_t   = (const float*)d_in[0];
    const float* pos_t = (const float*)d_in[1];
    const float* x_s   = (const float*)d_in[3];
    const float* pos_s = (const float*)d_in[4];
    const float* W1    = (const float*)d_in[6];
    const float* b1    = (const float*)d_in[7];
    const float* W2    = (const float*)d_in[8];
    const float* b2    = (const float*)d_in[9];
    const float* Ws    = (const float*)d_in[10];
    const float* bs    = (const float*)d_in[11];
    float* out = (float*)d_out;

    cudaFuncSetAttribute(gemm1_kernel, cudaFuncAttributeMaxDynamicSharedMemorySize, GSMEM);
    cudaFuncSetAttribute(gemm2_kernel, cudaFuncAttributeMaxDynamicSharedMemorySize, GSMEM);

    prep_weights<<<(CH * CIN + 255) / 256, 256>>>(W1, W2, Ws);
    knn_kernel<<<dim3(NTn / 64, Bn), 256>>>(x_t, pos_t, x_s, pos_s);
    gemm1_kernel<<<dim3(2, Mtot / 128), 256, GSMEM>>>(b1);
    gemm2_kernel<<<Mtot / 128, 256, GSMEM>>>(b2, bs, out);
}

// round 6
// speedup vs baseline: 2.2671x; 1.0697x over previous
#include <cuda_runtime.h>
#include <cuda_bf16.h>
#include <math.h>
#include <stdint.h>

#define Bn   8
#define NTn  8192
#define NSn  2048
#define CT   128
#define CS   256
#define CIN  384
#define CH   256
#define CO   128
#define Mtot (Bn * NTn)

// ---------------------------------------------------------------------------
// Device scratch (static — no runtime allocation)
// ---------------------------------------------------------------------------
__device__ __nv_bfloat16 g_comb_hi[(size_t)Mtot * CIN];
__device__ __nv_bfloat16 g_comb_lo[(size_t)Mtot * CIN];
__device__ __nv_bfloat16 g_hid_hi[(size_t)Mtot * CH];
__device__ __nv_bfloat16 g_hid_lo[(size_t)Mtot * CH];
__device__ __nv_bfloat16 g_w1t_hi[CH * CIN];
__device__ __nv_bfloat16 g_w1t_lo[CH * CIN];
__device__ __nv_bfloat16 g_w2t_hi[CO * CH];
__device__ __nv_bfloat16 g_w2t_lo[CO * CH];
__device__ __nv_bfloat16 g_wst_hi[CO * CIN];
__device__ __nv_bfloat16 g_wst_lo[CO * CIN];

// ---------------------------------------------------------------------------
// Helpers
// ---------------------------------------------------------------------------
__device__ __forceinline__ uint32_t smem_u32(const void* p) {
    uint32_t a;
    asm("{ .reg .u64 t; cvta.to.shared.u64 t, %1; cvt.u32.u64 %0, t; }" : "=r"(a) : "l"(p));
    return a;
}
#define CP16(smem_addr, gptr) \
    asm volatile("cp.async.cg.shared.global [%0], [%1], 16;" :: "r"(smem_addr), "l"(gptr))
#define CP_COMMIT() asm volatile("cp.async.commit_group;" ::: "memory")
#define CP_WAIT1()  asm volatile("cp.async.wait_group 1;" ::: "memory")
#define CP_WAIT0()  asm volatile("cp.async.wait_group 0;" ::: "memory")

__device__ __forceinline__ void ldsm4(uint32_t& r0, uint32_t& r1, uint32_t& r2, uint32_t& r3,
                                      uint32_t a) {
    asm volatile("ldmatrix.sync.aligned.m8n8.x4.shared.b16 {%0,%1,%2,%3}, [%4];"
                 : "=r"(r0), "=r"(r1), "=r"(r2), "=r"(r3) : "r"(a));
}
__device__ __forceinline__ void mma16816(float* d, uint32_t a0, uint32_t a1, uint32_t a2,
                                         uint32_t a3, uint32_t b0, uint32_t b1) {
    asm volatile("mma.sync.aligned.m16n8k16.row.col.f32.bf16.bf16.f32 "
                 "{%0,%1,%2,%3}, {%4,%5,%6,%7}, {%8,%9}, {%0,%1,%2,%3};"
                 : "+f"(d[0]), "+f"(d[1]), "+f"(d[2]), "+f"(d[3])
                 : "r"(a0), "r"(a1), "r"(a2), "r"(a3), "r"(b0), "r"(b1));
}
__device__ __forceinline__ void split2(float v, __nv_bfloat16& h, __nv_bfloat16& l) {
    h = __float2bfloat16(v);
    l = __float2bfloat16(v - __bfloat162float(h));
}
__device__ __forceinline__ uint32_t pack2(__nv_bfloat16 a, __nv_bfloat16 b) {
    __nv_bfloat162 t; t.x = a; t.y = b;
    return *reinterpret_cast<uint32_t*>(&t);
}

// ---------------------------------------------------------------------------
// SMEM stage layout: 4 tensors [128 rows x 32 bf16], padded pitch 80 B
// ---------------------------------------------------------------------------
#define PITCH  80
#define T_AH   0
#define T_AL   10240
#define T_BH   20480
#define T_BL   30720
#define STAGE  40960
#define GSMEM  (2 * STAGE)

__device__ __forceinline__ void load_stage(uint32_t st,
    const __nv_bfloat16* Ah, const __nv_bfloat16* Al,
    const __nv_bfloat16* Bh, const __nv_bfloat16* Bl,
    int ld, int k0, int tid)
{
    const __nv_bfloat16* gp[4] = {Ah, Al, Bh, Bl};
#pragma unroll
    for (int i = 0; i < 8; i++) {
        const int t  = i >> 1;
        const int rr = (i & 1) * 64 + (tid >> 2);
        const int q  = tid & 3;
        CP16(st + t * 10240 + rr * PITCH + q * 16, gp[t] + (size_t)rr * ld + k0 + q * 8);
    }
    CP_COMMIT();
}

// Restructured: consume each B ldmatrix immediately (live B regs 16 -> 4)
__device__ __forceinline__ void mma_stage(uint32_t st, int warp_m, int warp_n, int lane,
                                          float acc[2][8][4])
{
    const uint32_t arow0 = warp_m * 32 + (lane & 15);
    const uint32_t ahalf = (lane >> 4) * 16;
    const uint32_t brow  = warp_n * 64 + (lane & 7) + ((lane >> 4) << 3);
    const uint32_t bhalf = ((lane >> 3) & 1) * 16;
#pragma unroll
    for (int ks = 0; ks < 2; ks++) {
        const uint32_t ko = ks * 32;
#pragma unroll
        for (int p = 0; p < 3; p++) {          // Ah*Bh, Ah*Bl, Al*Bh
            const uint32_t aoff = (p == 2) ? T_AL : T_AH;
            const uint32_t boff = (p == 1) ? T_BL : T_BH;
            uint32_t a[2][4];
#pragma unroll
            for (int mt = 0; mt < 2; mt++)
                ldsm4(a[mt][0], a[mt][1], a[mt][2], a[mt][3],
                      st + aoff + (arow0 + mt * 16) * PITCH + ko + ahalf);
#pragma unroll
            for (int j = 0; j < 4; j++) {
                uint32_t b0, b1, b2, b3;
                ldsm4(b0, b1, b2, b3, st + boff + (brow + j * 16) * PITCH + ko + bhalf);
                mma16816(acc[0][2*j+0], a[0][0], a[0][1], a[0][2], a[0][3], b0, b1);
                mma16816(acc[0][2*j+1], a[0][0], a[0][1], a[0][2], a[0][3], b2, b3);
                mma16816(acc[1][2*j+0], a[1][0], a[1][1], a[1][2], a[1][3], b0, b1);
                mma16816(acc[1][2*j+1], a[1][0], a[1][1], a[1][2], a[1][3], b2, b3);
            }
        }
    }
}

__device__ __forceinline__ void gemm_phase(uint32_t sb,
    const __nv_bfloat16* Ah, const __nv_bfloat16* Al,
    const __nv_bfloat16* Bh, const __nv_bfloat16* Bl,
    int ld, int kchunks, int tid, int warp_m, int warp_n, int lane,
    float acc[2][8][4])
{
    load_stage(sb, Ah, Al, Bh, Bl, ld, 0, tid);
    for (int c = 0; c < kchunks; c++) {
        if (c + 1 < kchunks) {
            load_stage(sb + ((c + 1) & 1) * STAGE, Ah, Al, Bh, Bl, ld, (c + 1) * 32, tid);
            CP_WAIT1();
        } else {
            CP_WAIT0();
        }
        __syncthreads();
        mma_stage(sb + (c & 1) * STAGE, warp_m, warp_n, lane, acc);
        __syncthreads();
    }
}

// ---------------------------------------------------------------------------
// Weight prep
// ---------------------------------------------------------------------------
__global__ void prep_weights(const float* __restrict__ W1, const float* __restrict__ W2,
                             const float* __restrict__ Ws) {
    int i = blockIdx.x * blockDim.x + threadIdx.x;
    if (i < CH * CIN) {
        int n = i / CIN, k = i % CIN;
        split2(W1[(size_t)k * CH + n], g_w1t_hi[i], g_w1t_lo[i]);
    }
    if (i < CO * CH) {
        int n = i / CH, k = i % CH;
        split2(W2[(size_t)k * CO + n], g_w2t_hi[i], g_w2t_lo[i]);
    }
    if (i < CO * CIN) {
        int n = i / CIN, k = i % CIN;
        split2(Ws[(size_t)k * CO + n], g_wst_hi[i], g_wst_lo[i]);
    }
}

// ---------------------------------------------------------------------------
// KNN: 64 targets/CTA, 4-way source split, merge 12->3
// ---------------------------------------------------------------------------
__global__ __launch_bounds__(256) void knn_kernel(
    const float* __restrict__ x_t, const float* __restrict__ pos_t,
    const float* __restrict__ x_s, const float* __restrict__ pos_s)
{
    __shared__ float4 sp[NSn];
    __shared__ float  cd[64][12];
    __shared__ int    ci[64][12];
    __shared__ float  swt[64][3];
    __shared__ int    sit[64][3];

    const int b   = blockIdx.y;
    const int tid = threadIdx.x;

    const float* ps = pos_s + (size_t)b * NSn * 3;
    for (int j = tid; j < NSn; j += 256)
        sp[j] = make_float4(ps[3*j], ps[3*j+1], ps[3*j+2], 0.f);
    __syncthreads();

    const int tt = tid & 63, sq = tid >> 6;
    const int t0 = b * NTn + blockIdx.x * 64;
    const int t  = t0 + tt;
    const float tx = pos_t[3*t], ty = pos_t[3*t+1], tz = pos_t[3*t+2];

    float d0 = 3.4e38f, d1 = 3.4e38f, d2 = 3.4e38f;
    int   i0 = 0, i1 = 0, i2 = 0;
    const int jb = sq * 512;
#pragma unroll 4
    for (int j = jb; j < jb + 512; j++) {
        float4 s = sp[j];
        float dx = tx - s.x, dy = ty - s.y, dz = tz - s.z;
        float d  = fmaf(dx, dx, fmaf(dy, dy, dz * dz));
        if (d < d2) {
            if (d < d1) {
                d2 = d1; i2 = i1;
                if (d < d0) { d1 = d0; i1 = i0; d0 = d; i0 = j; }
                else        { d1 = d;  i1 = j; }
            } else { d2 = d; i2 = j; }
        }
    }
    cd[tt][sq*3+0] = d0; ci[tt][sq*3+0] = i0;
    cd[tt][sq*3+1] = d1; ci[tt][sq*3+1] = i1;
    cd[tt][sq*3+2] = d2; ci[tt][sq*3+2] = i2;
    __syncthreads();

    if (tid < 64) {
        float e0 = 3.4e38f, e1 = 3.4e38f, e2 = 3.4e38f;
        int   j0 = 0, j1 = 0, j2 = 0;
#pragma unroll
        for (int k = 0; k < 12; k++) {
            float d = cd[tid][k]; int ii = ci[tid][k];
            if (d < e2) {
                if (d < e1) {
                    e2 = e1; j2 = j1;
                    if (d < e0) { e1 = e0; j1 = j0; e0 = d; j0 = ii; }
                    else        { e1 = d;  j1 = ii; }
                } else { e2 = d; j2 = ii; }
            }
        }
        float w0 = 1.f / fmaxf(e0, 1e-16f);
        float w1 = 1.f / fmaxf(e1, 1e-16f);
        float w2 = 1.f / fmaxf(e2, 1e-16f);
        float inv = 1.f / (w0 + w1 + w2);
        swt[tid][0] = w0 * inv; swt[tid][1] = w1 * inv; swt[tid][2] = w2 * inv;
        sit[tid][0] = j0; sit[tid][1] = j1; sit[tid][2] = j2;
    }
    __syncthreads();

    const float* xsb = x_s + (size_t)b * NSn * CS;
    const int c = tid;
    for (int u = 0; u < 64; u++) {
        const int tg = t0 + u;
        float v = swt[u][0] * xsb[(size_t)sit[u][0] * CS + c]
                + swt[u][1] * xsb[(size_t)sit[u][1] * CS + c]
                + swt[u][2] * xsb[(size_t)sit[u][2] * CS + c];
        __nv_bfloat16 h, l;
        split2(v, h, l);
        g_comb_hi[(size_t)tg * CIN + CT + c] = h;
        g_comb_lo[(size_t)tg * CIN + CT + c] = l;
        if (c < CT) {
            split2(x_t[(size_t)tg * CT + c], h, l);
            g_comb_hi[(size_t)tg * CIN + c] = h;
            g_comb_lo[(size_t)tg * CIN + c] = l;
        }
    }
}

// ---------------------------------------------------------------------------
// GEMM1: hid = relu(comb @ W1 + b1), M=65536 N=256 K=384
// ---------------------------------------------------------------------------
__global__ __launch_bounds__(256, 2) void gemm1_kernel(const float* __restrict__ b1) {
    extern __shared__ char smem[];
    const uint32_t sb = smem_u32(smem);
    const int tid = threadIdx.x, lane = tid & 31, wid = tid >> 5;
    const int warp_m = wid >> 1, warp_n = wid & 1;
    const int bn = blockIdx.x * 128, bm = blockIdx.y * 128;

    float acc[2][8][4] = {};
    gemm_phase(sb, g_comb_hi + (size_t)bm * CIN, g_comb_lo + (size_t)bm * CIN,
               g_w1t_hi + (size_t)bn * CIN, g_w1t_lo + (size_t)bn * CIN,
               CIN, 12, tid, warp_m, warp_n, lane, acc);

    uint32_t* dh = (uint32_t*)g_hid_hi;
    uint32_t* dl = (uint32_t*)g_hid_lo;
#pragma unroll
    for (int mt = 0; mt < 2; mt++) {
#pragma unroll
        for (int nt = 0; nt < 8; nt++) {
            const int col = bn + warp_n * 64 + nt * 8 + (lane & 3) * 2;
            const float bb0 = __ldg(b1 + col), bb1 = __ldg(b1 + col + 1);
            const int row = bm + warp_m * 32 + mt * 16 + (lane >> 2);
#pragma unroll
            for (int h = 0; h < 2; h++) {
                const int r = row + h * 8;
                float v0 = fmaxf(acc[mt][nt][2*h+0] + bb0, 0.f);
                float v1 = fmaxf(acc[mt][nt][2*h+1] + bb1, 0.f);
                __nv_bfloat16 h0, l0, h1, l1;
                split2(v0, h0, l0);
                split2(v1, h1, l1);
                const size_t w = ((size_t)r * CH + col) >> 1;
                dh[w] = pack2(h0, h1);
                dl[w] = pack2(l0, l1);
            }
        }
    }
}

// ---------------------------------------------------------------------------
// GEMM2: out = relu(hid @ W2 + comb @ Ws + b2 + bs), M=65536 N=128
// ---------------------------------------------------------------------------
__global__ __launch_bounds__(256, 2) void gemm2_kernel(
    const float* __restrict__ b2, const float* __restrict__ bs, float* __restrict__ out)
{
    extern __shared__ char smem[];
    const uint32_t sb = smem_u32(smem);
    const int tid = threadIdx.x, lane = tid & 31, wid = tid >> 5;
    const int warp_m = wid >> 1, warp_n = wid & 1;
    const int bm = blockIdx.x * 128;

    float acc[2][8][4] = {};
    gemm_phase(sb, g_hid_hi + (size_t)bm * CH, g_hid_lo + (size_t)bm * CH,
               g_w2t_hi, g_w2t_lo, CH, 8, tid, warp_m, warp_n, lane, acc);
    gemm_phase(sb, g_comb_hi + (size_t)bm * CIN, g_comb_lo + (size_t)bm * CIN,
               g_wst_hi, g_wst_lo, CIN, 12, tid, warp_m, warp_n, lane, acc);

#pragma unroll
    for (int mt = 0; mt < 2; mt++) {
#pragma unroll
        for (int nt = 0; nt < 8; nt++) {
            const int col = warp_n * 64 + nt * 8 + (lane & 3) * 2;
            const float bb0 = __ldg(b2 + col) + __ldg(bs + col);
            const float bb1 = __ldg(b2 + col + 1) + __ldg(bs + col + 1);
            const int row = bm + warp_m * 32 + mt * 16 + (lane >> 2);
#pragma unroll
            for (int h = 0; h < 2; h++) {
                const int r = row + h * 8;
                float2 v;
                v.x = fmaxf(acc[mt][nt][2*h+0] + bb0, 0.f);
                v.y = fmaxf(acc[mt][nt][2*h+1] + bb1, 0.f);
                *(float2*)&out[(size_t)r * CO + col] = v;
            }
        }
    }
}

// ---------------------------------------------------------------------------
extern "C" void kernel_launch(void* const* d_in, const int* in_sizes, int n_in,
                              void* d_out, int out_size)
{
    const float* x_t   = (const float*)d_in[0];
    const float* pos_t = (const float*)d_in[1];
    const float* x_s   = (const float*)d_in[3];
    const float* pos_s = (const float*)d_in[4];
    const float* W1    = (const float*)d_in[6];
    const float* b1    = (const float*)d_in[7];
    const float* W2    = (const float*)d_in[8];
    const float* b2    = (const float*)d_in[9];
    const float* Ws    = (const float*)d_in[10];
    const float* bs    = (const float*)d_in[11];
    float* out = (float*)d_out;

    cudaFuncSetAttribute(gemm1_kernel, cudaFuncAttributeMaxDynamicSharedMemorySize, GSMEM);
    cudaFuncSetAttribute(gemm2_kernel, cudaFuncAttributeMaxDynamicSharedMemorySize, GSMEM);

    prep_weights<<<(CH * CIN + 255) / 256, 256>>>(W1, W2, Ws);
    knn_kernel<<<dim3(NTn / 64, Bn), 256>>>(x_t, pos_t, x_s, pos_s);
    gemm1_kernel<<<dim3(2, Mtot / 128), 256, GSMEM>>>(b1);
    gemm2_kernel<<<Mtot / 128, 256, GSMEM>>>(b2, bs, out);
}